// round 10
// baseline (speedup 1.0000x reference)
#include <cuda_runtime.h>
#include <cuda_bf16.h>
#include <cstdint>

// Problem constants
#define BATCH   4096
#define DIN     2048
#define HID     16384
#define KTOP    64
#define TSEL    80
#define CAP     256
#define NCHK    4
#define CHKROWS (BATCH / NCHK)    // 1024

// ---------------- scratch -----------------------------------------------------
__device__ __nv_bfloat16  g_xb[(size_t)BATCH * DIN];          // 16 MB
__device__ __nv_bfloat16  g_wb[(size_t)HID * DIN];            // 64 MB
__device__ unsigned short g_keys[(size_t)BATCH * HID];        // 128 MB
__device__ float          g_wdt[(size_t)HID * DIN];           // 128 MB
__device__ int            g_topi[(size_t)BATCH * KTOP];
__device__ float          g_topv[(size_t)BATCH * KTOP];

// ---------------- helpers -----------------------------------------------------
__device__ __forceinline__ unsigned su32(const void* p) {
    return (unsigned)__cvta_generic_to_shared(p);
}
__device__ __forceinline__ unsigned short f2key16(float f) {
    unsigned u = __float_as_uint(f);
    u = (u & 0x80000000u) ? ~u : (u | 0x80000000u);
    return (unsigned short)(u >> 16);
}

#define CP16(dst, src) asm volatile( \
    "cp.async.cg.shared.global [%0], [%1], 16;\n" :: "r"(dst), "l"(src))
#define CP_COMMIT() asm volatile("cp.async.commit_group;\n" ::)
#define CP_WAIT(N)  asm volatile("cp.async.wait_group %0;\n" :: "n"(N))

// ---------------- kernels 1/2: fp32 -> bf16 -----------------------------------
__global__ void conv_bf16_kernel(const float* __restrict__ in, int which, size_t n4) {
    __nv_bfloat16* out = which ? g_wb : g_xb;
    __nv_bfloat162* o2 = (__nv_bfloat162*)out;
    for (size_t i = (size_t)blockIdx.x * blockDim.x + threadIdx.x;
         i < n4; i += (size_t)gridDim.x * blockDim.x) {
        float4 v = ((const float4*)in)[i];
        o2[2 * i]     = __nv_bfloat162(__float2bfloat16_rn(v.x), __float2bfloat16_rn(v.y));
        o2[2 * i + 1] = __nv_bfloat162(__float2bfloat16_rn(v.z), __float2bfloat16_rn(v.w));
    }
}

// ---------------- kernel 3: transpose W_dec -----------------------------------
__global__ void transpose_wdec_kernel(const float* __restrict__ W) {
    __shared__ float tile[32][33];
    int j0 = blockIdx.x * 32, d0 = blockIdx.y * 32;
    int tx = threadIdx.x, ty = threadIdx.y;
#pragma unroll
    for (int r = 0; r < 32; r += 8)
        tile[ty + r][tx] = W[(size_t)(d0 + ty + r) * HID + j0 + tx];
    __syncthreads();
#pragma unroll
    for (int r = 0; r < 32; r += 8)
        g_wdt[(size_t)(j0 + ty + r) * DIN + d0 + tx] = tile[tx][ty + r];
}

// ---------------- kernel 4: bf16 mma.sync GEMM -> u16 keys ---------------------
#define BM 128
#define BN 128
#define BK 32
#define LDS 40   // padded bf16 row (80B stride)

__global__ __launch_bounds__(256) void gemm_enc_kernel(const float* __restrict__ benc,
                                                       int bm0) {
    __shared__ __align__(16) __nv_bfloat16 As[2][BM * LDS];
    __shared__ __align__(16) __nv_bfloat16 Bs[2][BN * LDS];

    const int t = threadIdx.x;
    const int lane = t & 31, wid = t >> 5;
    const int wm = wid & 1, wn = wid >> 1;         // 2 x 4 warp grid, warp tile 64x32
    const int bm = blockIdx.x + bm0, bn = blockIdx.y;

    float acc[4][4][4];
#pragma unroll
    for (int i = 0; i < 4; i++)
#pragma unroll
        for (int j = 0; j < 4; j++)
#pragma unroll
            for (int r = 0; r < 4; r++) acc[i][j][r] = 0.f;

    auto load_stage = [&](int s, int kt) {
#pragma unroll
        for (int i = 0; i < 2; i++) {
            int cid = i * 256 + t;
            int row = cid >> 2, ch = cid & 3;
            const __nv_bfloat16* srcA = g_xb + (size_t)(bm * BM + row) * DIN + kt * BK + ch * 8;
            CP16(su32(&As[s][row * LDS + ch * 8]), srcA);
        }
#pragma unroll
        for (int i = 0; i < 2; i++) {
            int cid = i * 256 + t;
            int row = cid >> 2, ch = cid & 3;
            const __nv_bfloat16* srcB = g_wb + (size_t)(bn * BN + row) * DIN + kt * BK + ch * 8;
            CP16(su32(&Bs[s][row * LDS + ch * 8]), srcB);
        }
        CP_COMMIT();
    };

    auto compute = [&](int s) {
#pragma unroll
        for (int ks = 0; ks < 2; ks++) {
            unsigned a[4][4], b[4][2];
#pragma unroll
            for (int im = 0; im < 4; im++) {
                unsigned addr = su32(&As[s][(wm * 64 + im * 16 + (lane & 15)) * LDS +
                                            ks * 16 + (lane >> 4) * 8]);
                asm volatile("ldmatrix.sync.aligned.m8n8.x4.shared.b16 {%0,%1,%2,%3}, [%4];"
                             : "=r"(a[im][0]), "=r"(a[im][1]), "=r"(a[im][2]), "=r"(a[im][3])
                             : "r"(addr));
            }
#pragma unroll
            for (int in = 0; in < 4; in++) {
                unsigned addr = su32(&Bs[s][(wn * 32 + in * 8 + (lane & 7)) * LDS +
                                            ks * 16 + ((lane >> 3) & 1) * 8]);
                asm volatile("ldmatrix.sync.aligned.m8n8.x2.shared.b16 {%0,%1}, [%2];"
                             : "=r"(b[in][0]), "=r"(b[in][1]) : "r"(addr));
            }
#pragma unroll
            for (int im = 0; im < 4; im++)
#pragma unroll
                for (int in = 0; in < 4; in++) {
                    asm volatile(
                        "mma.sync.aligned.m16n8k16.row.col.f32.bf16.bf16.f32 "
                        "{%0,%1,%2,%3}, {%4,%5,%6,%7}, {%8,%9}, {%0,%1,%2,%3};"
                        : "+f"(acc[im][in][0]), "+f"(acc[im][in][1]),
                          "+f"(acc[im][in][2]), "+f"(acc[im][in][3])
                        : "r"(a[im][0]), "r"(a[im][1]), "r"(a[im][2]), "r"(a[im][3]),
                          "r"(b[in][0]), "r"(b[in][1]));
                }
        }
    };

    const int KT = DIN / BK;  // 64
    load_stage(0, 0);
    for (int kt = 0; kt < KT; kt++) {
        int cur = kt & 1;
        if (kt + 1 < KT) {
            load_stage(cur ^ 1, kt + 1);
            CP_WAIT(1);
        } else {
            CP_WAIT(0);
        }
        __syncthreads();
        compute(cur);
        __syncthreads();
    }

    const int r0base = bm * BM + wm * 64;
    const int c0base = bn * BN + wn * 32;
#pragma unroll
    for (int im = 0; im < 4; im++) {
#pragma unroll
        for (int in = 0; in < 4; in++) {
            int r0 = r0base + im * 16 + (lane >> 2);
            int c0 = c0base + in * 8 + (lane & 3) * 2;
            float b0 = benc[c0], b1 = benc[c0 + 1];
            unsigned p0 = (unsigned)f2key16(acc[im][in][0] + b0) |
                          ((unsigned)f2key16(acc[im][in][1] + b1) << 16);
            unsigned p1 = (unsigned)f2key16(acc[im][in][2] + b0) |
                          ((unsigned)f2key16(acc[im][in][3] + b1) << 16);
            *(unsigned*)(g_keys + (size_t)r0 * HID + c0) = p0;
            *(unsigned*)(g_keys + (size_t)(r0 + 8) * HID + c0) = p1;
        }
    }
}

// ---------------- kernel 5: per-row select + exact recompute + h write ---------
__global__ __launch_bounds__(256) void select_kernel(
    const float* __restrict__ x, const float* __restrict__ Wenc,
    const float* __restrict__ benc, float* __restrict__ h_out, int row0) {

    __shared__ __align__(16) unsigned short sk[HID];
    __shared__ __align__(16) float xs[DIN];
    __shared__ int hist[256];
    __shared__ int cidx[CAP];
    __shared__ float cval[CAP];
    __shared__ float sv[256];
    __shared__ int si[256];
    __shared__ int s_cnt, s_selhi, s_rem;
    __shared__ unsigned s_thr;

    const int row = blockIdx.x + row0;
    const int t = threadIdx.x;
    const int lane = t & 31, wid = t >> 5;

    {
        const uint4* gk = (const uint4*)(g_keys + (size_t)row * HID);
        uint4* skv = (uint4*)sk;
#pragma unroll
        for (int i = 0; i < 8; i++) skv[t + i * 256] = gk[t + i * 256];
        const float4* gx = (const float4*)(x + (size_t)row * DIN);
        float4* xsv = (float4*)xs;
        xsv[t] = gx[t];
        xsv[t + 256] = gx[t + 256];
    }
    hist[t] = 0;
    if (t == 0) s_cnt = 0;
    __syncthreads();

    for (int i = t; i < HID; i += 256) atomicAdd(&hist[sk[i] >> 8], 1);
    __syncthreads();
    if (t == 0) {
        int cum = 0;
        s_selhi = 0; s_rem = TSEL;
        for (int b = 255; b >= 0; b--) {
            int hb = hist[b];
            if (cum + hb >= TSEL) { s_selhi = b; s_rem = TSEL - cum; break; }
            cum += hb;
        }
    }
    __syncthreads();
    int selhi = s_selhi, rem = s_rem;
    hist[t] = 0;
    __syncthreads();

    for (int i = t; i < HID; i += 256) {
        unsigned k = sk[i];
        if ((int)(k >> 8) == selhi) atomicAdd(&hist[k & 255], 1);
    }
    __syncthreads();
    if (t == 0) {
        int cum = 0, sello = 0;
        for (int b = 255; b >= 0; b--) {
            int hb = hist[b];
            if (cum + hb >= rem) { sello = b; break; }
            cum += hb;
        }
        s_thr = ((unsigned)selhi << 8) | (unsigned)sello;
    }
    __syncthreads();
    unsigned thr = s_thr;

    for (int i = t; i < HID; i += 256) {
        if ((unsigned)sk[i] >= thr) {
            int p = atomicAdd(&s_cnt, 1);
            if (p < CAP) cidx[p] = i;
        }
    }
    __syncthreads();
    int C = s_cnt < CAP ? s_cnt : CAP;

    const float4* xs4 = (const float4*)xs;
    for (int c = wid; c < C; c += 8) {
        int idx = cidx[c];
        const float4* w4 = (const float4*)(Wenc + (size_t)idx * DIN);
        float s = 0.f;
#pragma unroll 4
        for (int i = lane; i < DIN / 4; i += 32) {
            float4 w = w4[i], xv = xs4[i];
            s += w.x * xv.x + w.y * xv.y + w.z * xv.z + w.w * xv.w;
        }
#pragma unroll
        for (int off = 16; off; off >>= 1) s += __shfl_xor_sync(0xffffffffu, s, off);
        if (lane == 0) cval[c] = s + benc[idx];
    }
    __syncthreads();

    sv[t] = (t < C) ? cval[t] : -__int_as_float(0x7f800000);
    si[t] = (t < C) ? cidx[t] : 0x7fffffff;
    __syncthreads();
    for (int k = 2; k <= 256; k <<= 1) {
        for (int j = k >> 1; j > 0; j >>= 1) {
            int ixj = t ^ j;
            if (ixj > t) {
                float v1 = sv[t], v2 = sv[ixj];
                int i1 = si[t], i2 = si[ixj];
                bool g = (v1 > v2) || (v1 == v2 && i1 < i2);
                bool dirDesc = ((t & k) == 0);
                if (dirDesc ? (!g) : g) {
                    sv[t] = v2; sv[ixj] = v1;
                    si[t] = i2; si[ixj] = i1;
                }
            }
            __syncthreads();
        }
    }

    float* hrow = h_out + (size_t)row * HID;
    {
        float4 z = make_float4(0.f, 0.f, 0.f, 0.f);
        float4* h4 = (float4*)hrow;
#pragma unroll
        for (int i = 0; i < 16; i++) h4[t + i * 256] = z;
    }
    __syncthreads();
    if (t < KTOP) {
        hrow[si[t]] = sv[t];
        g_topi[(size_t)row * KTOP + t] = si[t];
        g_topv[(size_t)row * KTOP + t] = sv[t];
    }
}

// ---------------- kernel 6: sparse decoder ------------------------------------
__global__ __launch_bounds__(256) void decode_kernel(
    const float* __restrict__ bdec, float* __restrict__ xhat_out, int row0) {
    __shared__ int sid[KTOP];
    __shared__ float sval[KTOP];
    const int row = blockIdx.x + row0;
    const int t = threadIdx.x;
    if (t < KTOP) {
        sid[t] = g_topi[(size_t)row * KTOP + t];
        sval[t] = g_topv[(size_t)row * KTOP + t];
    }
    __syncthreads();

    const int base = t * 8;
    float4 a0 = ((const float4*)(bdec + base))[0];
    float4 a1 = ((const float4*)(bdec + base))[1];
#pragma unroll 4
    for (int j = 0; j < KTOP; j++) {
        float v = sval[j];
        const float4* wr = (const float4*)(g_wdt + (size_t)sid[j] * DIN + base);
        float4 w0 = wr[0], w1 = wr[1];
        a0.x += v * w0.x; a0.y += v * w0.y; a0.z += v * w0.z; a0.w += v * w0.w;
        a1.x += v * w1.x; a1.y += v * w1.y; a1.z += v * w1.z; a1.w += v * w1.w;
    }
    float4* o = (float4*)(xhat_out + (size_t)row * DIN + base);
    o[0] = a0; o[1] = a1;
}

// ---------------- launch -------------------------------------------------------
extern "C" void kernel_launch(void* const* d_in, const int* in_sizes, int n_in,
                              void* d_out, int out_size) {
    const float* x    = (const float*)d_in[0];
    const float* Wenc = (const float*)d_in[1];
    const float* benc = (const float*)d_in[2];
    const float* Wdec = (const float*)d_in[3];
    const float* bdec = (const float*)d_in[4];

    float* h    = (float*)d_out;
    float* xhat = h + (size_t)BATCH * HID;

    static cudaStream_t s1, s2;
    static cudaEvent_t ev0, ev1, evj, evg[NCHK];
    static int inited = 0;
    if (!inited) {
        cudaStreamCreateWithFlags(&s1, cudaStreamNonBlocking);
        cudaStreamCreateWithFlags(&s2, cudaStreamNonBlocking);
        cudaEventCreateWithFlags(&ev0, cudaEventDisableTiming);
        cudaEventCreateWithFlags(&ev1, cudaEventDisableTiming);
        cudaEventCreateWithFlags(&evj, cudaEventDisableTiming);
        for (int c = 0; c < NCHK; c++)
            cudaEventCreateWithFlags(&evg[c], cudaEventDisableTiming);
        inited = 1;
    }

    // fork both worker streams off the capture-origin stream
    cudaEventRecord(ev0, 0);
    cudaStreamWaitEvent(s1, ev0, 0);
    cudaStreamWaitEvent(s2, ev0, 0);

    // s1: bf16 conversions + GEMM chunks (tensor-bound branch)
    {
        size_t n4 = (size_t)BATCH * DIN / 4;
        conv_bf16_kernel<<<(unsigned)((n4 + 1023) / 1024), 256, 0, s1>>>(x, 0, n4);
    }
    {
        size_t n4 = (size_t)HID * DIN / 4;
        conv_bf16_kernel<<<8192, 256, 0, s1>>>(Wenc, 1, n4);
    }
    for (int c = 0; c < NCHK; c++) {
        gemm_enc_kernel<<<dim3(CHKROWS / BM, HID / BN), 256, 0, s1>>>(
            benc, c * (CHKROWS / BM));
        cudaEventRecord(evg[c], s1);
    }
    cudaEventRecord(ev1, s1);

    // s2: transpose (overlaps first GEMM chunk) + per-chunk select/decode
    transpose_wdec_kernel<<<dim3(HID / 32, DIN / 32), dim3(32, 8), 0, s2>>>(Wdec);
    for (int c = 0; c < NCHK; c++) {
        cudaStreamWaitEvent(s2, evg[c], 0);
        select_kernel<<<CHKROWS, 256, 0, s2>>>(x, Wenc, benc, h, c * CHKROWS);
        decode_kernel<<<CHKROWS, 256, 0, s2>>>(bdec, xhat, c * CHKROWS);
    }
    cudaEventRecord(evj, s2);

    // join both branches back to the capture-origin stream
    cudaStreamWaitEvent(0, ev1, 0);
    cudaStreamWaitEvent(0, evj, 0);
}

// round 12
// speedup vs baseline: 1.0678x; 1.0678x over previous
#include <cuda_runtime.h>
#include <cuda_fp16.h>
#include <cstdint>

// Problem constants
#define BATCH   4096
#define DIN     2048
#define HID     16384
#define KTOP    64
#define TSEL    72
#define CAP     256

// ---------------- scratch -----------------------------------------------------
__device__ __half         g_xh[(size_t)BATCH * DIN];          // 16 MB
__device__ __half         g_wh[(size_t)HID * DIN];            // 64 MB
__device__ unsigned short g_keys[(size_t)BATCH * HID];        // 128 MB
__device__ float          g_wdt[(size_t)HID * DIN];           // 128 MB
__device__ int            g_topi[(size_t)BATCH * KTOP];
__device__ float          g_topv[(size_t)BATCH * KTOP];

// ---------------- helpers -----------------------------------------------------
__device__ __forceinline__ unsigned su32(const void* p) {
    return (unsigned)__cvta_generic_to_shared(p);
}
__device__ __forceinline__ unsigned short f2key16(float f) {
    unsigned u = __float_as_uint(f);
    u = (u & 0x80000000u) ? ~u : (u | 0x80000000u);
    return (unsigned short)(u >> 16);
}

#define CP16(dst, src) asm volatile( \
    "cp.async.cg.shared.global [%0], [%1], 16;\n" :: "r"(dst), "l"(src))
#define CP_COMMIT() asm volatile("cp.async.commit_group;\n" ::)
#define CP_WAIT(N)  asm volatile("cp.async.wait_group %0;\n" :: "n"(N))

// ---------------- kernels 1/2: fp32 -> fp16 -----------------------------------
__global__ void conv_h_kernel(const float* __restrict__ in, int which, size_t n4) {
    __half* out = which ? g_wh : g_xh;
    __half2* o2 = (__half2*)out;
    for (size_t i = (size_t)blockIdx.x * blockDim.x + threadIdx.x;
         i < n4; i += (size_t)gridDim.x * blockDim.x) {
        float4 v = ((const float4*)in)[i];
        o2[2 * i]     = __floats2half2_rn(v.x, v.y);
        o2[2 * i + 1] = __floats2half2_rn(v.z, v.w);
    }
}

// ---------------- kernel 3: transpose W_dec -----------------------------------
__global__ void transpose_wdec_kernel(const float* __restrict__ W) {
    __shared__ float tile[32][33];
    int j0 = blockIdx.x * 32, d0 = blockIdx.y * 32;
    int tx = threadIdx.x, ty = threadIdx.y;
#pragma unroll
    for (int r = 0; r < 32; r += 8)
        tile[ty + r][tx] = W[(size_t)(d0 + ty + r) * HID + j0 + tx];
    __syncthreads();
#pragma unroll
    for (int r = 0; r < 32; r += 8)
        g_wdt[(size_t)(j0 + ty + r) * DIN + d0 + tx] = tile[tx][ty + r];
}

// ---------------- kernel 4: fp16 mma.sync GEMM (f16 acc) -> u16 keys -----------
// CTA tile 128x128, BK=32, 8 warps (2x4), warp tile 64x32, double-buffered.
// f16 accumulators promoted to fp32 every 8 K-chunks (256 K-elems).
#define BM 128
#define BN 128
#define BK 32
#define LDS 40   // padded fp16 row (80B stride)

__global__ __launch_bounds__(256) void gemm_enc_kernel(const float* __restrict__ benc) {
    __shared__ __align__(16) __half As[2][BM * LDS];
    __shared__ __align__(16) __half Bs[2][BN * LDS];

    const int t = threadIdx.x;
    const int lane = t & 31, wid = t >> 5;
    const int wm = wid & 1, wn = wid >> 1;         // 2 x 4 warp grid, warp tile 64x32
    const int bm = blockIdx.x, bn = blockIdx.y;

    float accf[4][4][4];
    unsigned acch[4][4][2];
#pragma unroll
    for (int i = 0; i < 4; i++)
#pragma unroll
        for (int j = 0; j < 4; j++) {
#pragma unroll
            for (int r = 0; r < 4; r++) accf[i][j][r] = 0.f;
            acch[i][j][0] = 0u; acch[i][j][1] = 0u;
        }

    auto load_stage = [&](int s, int kt) {
#pragma unroll
        for (int i = 0; i < 2; i++) {
            int cid = i * 256 + t;
            int row = cid >> 2, ch = cid & 3;
            const __half* srcA = g_xh + (size_t)(bm * BM + row) * DIN + kt * BK + ch * 8;
            CP16(su32(&As[s][row * LDS + ch * 8]), srcA);
        }
#pragma unroll
        for (int i = 0; i < 2; i++) {
            int cid = i * 256 + t;
            int row = cid >> 2, ch = cid & 3;
            const __half* srcB = g_wh + (size_t)(bn * BN + row) * DIN + kt * BK + ch * 8;
            CP16(su32(&Bs[s][row * LDS + ch * 8]), srcB);
        }
        CP_COMMIT();
    };

    auto compute = [&](int s) {
#pragma unroll
        for (int ks = 0; ks < 2; ks++) {
            unsigned a[4][4], b[4][2];
#pragma unroll
            for (int im = 0; im < 4; im++) {
                unsigned addr = su32(&As[s][(wm * 64 + im * 16 + (lane & 15)) * LDS +
                                            ks * 16 + (lane >> 4) * 8]);
                asm volatile("ldmatrix.sync.aligned.m8n8.x4.shared.b16 {%0,%1,%2,%3}, [%4];"
                             : "=r"(a[im][0]), "=r"(a[im][1]), "=r"(a[im][2]), "=r"(a[im][3])
                             : "r"(addr));
            }
#pragma unroll
            for (int in = 0; in < 4; in++) {
                unsigned addr = su32(&Bs[s][(wn * 32 + in * 8 + (lane & 7)) * LDS +
                                            ks * 16 + ((lane >> 3) & 1) * 8]);
                asm volatile("ldmatrix.sync.aligned.m8n8.x2.shared.b16 {%0,%1}, [%2];"
                             : "=r"(b[in][0]), "=r"(b[in][1]) : "r"(addr));
            }
#pragma unroll
            for (int im = 0; im < 4; im++)
#pragma unroll
                for (int in = 0; in < 4; in++) {
                    asm volatile(
                        "mma.sync.aligned.m16n8k16.row.col.f16.f16.f16.f16 "
                        "{%0,%1}, {%2,%3,%4,%5}, {%6,%7}, {%0,%1};"
                        : "+r"(acch[im][in][0]), "+r"(acch[im][in][1])
                        : "r"(a[im][0]), "r"(a[im][1]), "r"(a[im][2]), "r"(a[im][3]),
                          "r"(b[in][0]), "r"(b[in][1]));
                }
        }
    };

    auto promote = [&]() {
#pragma unroll
        for (int im = 0; im < 4; im++)
#pragma unroll
            for (int in = 0; in < 4; in++) {
                float2 lo = __half22float2(*(__half2*)&acch[im][in][0]);
                float2 hi = __half22float2(*(__half2*)&acch[im][in][1]);
                accf[im][in][0] += lo.x; accf[im][in][1] += lo.y;
                accf[im][in][2] += hi.x; accf[im][in][3] += hi.y;
                acch[im][in][0] = 0u; acch[im][in][1] = 0u;
            }
    };

    const int KT = DIN / BK;  // 64
    load_stage(0, 0);
    for (int kt = 0; kt < KT; kt++) {
        int cur = kt & 1;
        if (kt + 1 < KT) {
            load_stage(cur ^ 1, kt + 1);
            CP_WAIT(1);
        } else {
            CP_WAIT(0);
        }
        __syncthreads();
        compute(cur);
        if ((kt & 7) == 7) promote();   // spill f16 accs to fp32 every 256 K-elems
        __syncthreads();
    }

    const int r0base = bm * BM + wm * 64;
    const int c0base = bn * BN + wn * 32;
#pragma unroll
    for (int im = 0; im < 4; im++) {
#pragma unroll
        for (int in = 0; in < 4; in++) {
            int r0 = r0base + im * 16 + (lane >> 2);
            int c0 = c0base + in * 8 + (lane & 3) * 2;
            float b0 = benc[c0], b1 = benc[c0 + 1];
            unsigned p0 = (unsigned)f2key16(accf[im][in][0] + b0) |
                          ((unsigned)f2key16(accf[im][in][1] + b1) << 16);
            unsigned p1 = (unsigned)f2key16(accf[im][in][2] + b0) |
                          ((unsigned)f2key16(accf[im][in][3] + b1) << 16);
            *(unsigned*)(g_keys + (size_t)r0 * HID + c0) = p0;
            *(unsigned*)(g_keys + (size_t)(r0 + 8) * HID + c0) = p1;
        }
    }
}

// ---------------- kernel 5: per-row select + exact recompute + h write ---------
__global__ __launch_bounds__(256) void select_kernel(
    const float* __restrict__ x, const float* __restrict__ Wenc,
    const float* __restrict__ benc, float* __restrict__ h_out) {

    __shared__ __align__(16) unsigned short sk[HID];
    __shared__ __align__(16) float xs[DIN];
    __shared__ int hist[256];
    __shared__ int cidx[CAP];
    __shared__ float cval[CAP];
    __shared__ float sv[256];
    __shared__ int si[256];
    __shared__ int s_cnt, s_selhi, s_rem;
    __shared__ unsigned s_thr;

    const int row = blockIdx.x;
    const int t = threadIdx.x;
    const int lane = t & 31, wid = t >> 5;

    {
        const uint4* gk = (const uint4*)(g_keys + (size_t)row * HID);
        uint4* skv = (uint4*)sk;
#pragma unroll
        for (int i = 0; i < 8; i++) skv[t + i * 256] = gk[t + i * 256];
        const float4* gx = (const float4*)(x + (size_t)row * DIN);
        float4* xsv = (float4*)xs;
        xsv[t] = gx[t];
        xsv[t + 256] = gx[t + 256];
    }
    hist[t] = 0;
    if (t == 0) s_cnt = 0;
    __syncthreads();

    for (int i = t; i < HID; i += 256) atomicAdd(&hist[sk[i] >> 8], 1);
    __syncthreads();
    if (t == 0) {
        int cum = 0;
        s_selhi = 0; s_rem = TSEL;
        for (int b = 255; b >= 0; b--) {
            int hb = hist[b];
            if (cum + hb >= TSEL) { s_selhi = b; s_rem = TSEL - cum; break; }
            cum += hb;
        }
    }
    __syncthreads();
    int selhi = s_selhi, rem = s_rem;
    hist[t] = 0;
    __syncthreads();

    for (int i = t; i < HID; i += 256) {
        unsigned k = sk[i];
        if ((int)(k >> 8) == selhi) atomicAdd(&hist[k & 255], 1);
    }
    __syncthreads();
    if (t == 0) {
        int cum = 0, sello = 0;
        for (int b = 255; b >= 0; b--) {
            int hb = hist[b];
            if (cum + hb >= rem) { sello = b; break; }
            cum += hb;
        }
        s_thr = ((unsigned)selhi << 8) | (unsigned)sello;
    }
    __syncthreads();
    unsigned thr = s_thr;

    for (int i = t; i < HID; i += 256) {
        if ((unsigned)sk[i] >= thr) {
            int p = atomicAdd(&s_cnt, 1);
            if (p < CAP) cidx[p] = i;
        }
    }
    __syncthreads();
    int C = s_cnt < CAP ? s_cnt : CAP;

    const float4* xs4 = (const float4*)xs;
    for (int c = wid; c < C; c += 8) {
        int idx = cidx[c];
        const float4* w4 = (const float4*)(Wenc + (size_t)idx * DIN);
        float s = 0.f;
#pragma unroll 4
        for (int i = lane; i < DIN / 4; i += 32) {
            float4 w = w4[i], xv = xs4[i];
            s += w.x * xv.x + w.y * xv.y + w.z * xv.z + w.w * xv.w;
        }
#pragma unroll
        for (int off = 16; off; off >>= 1) s += __shfl_xor_sync(0xffffffffu, s, off);
        if (lane == 0) cval[c] = s + benc[idx];
    }
    __syncthreads();

    sv[t] = (t < C) ? cval[t] : -__int_as_float(0x7f800000);
    si[t] = (t < C) ? cidx[t] : 0x7fffffff;
    __syncthreads();
    for (int k = 2; k <= 256; k <<= 1) {
        for (int j = k >> 1; j > 0; j >>= 1) {
            int ixj = t ^ j;
            if (ixj > t) {
                float v1 = sv[t], v2 = sv[ixj];
                int i1 = si[t], i2 = si[ixj];
                bool g = (v1 > v2) || (v1 == v2 && i1 < i2);
                bool dirDesc = ((t & k) == 0);
                if (dirDesc ? (!g) : g) {
                    sv[t] = v2; sv[ixj] = v1;
                    si[t] = i2; si[ixj] = i1;
                }
            }
            __syncthreads();
        }
    }

    float* hrow = h_out + (size_t)row * HID;
    {
        float4 z = make_float4(0.f, 0.f, 0.f, 0.f);
        float4* h4 = (float4*)hrow;
#pragma unroll
        for (int i = 0; i < 16; i++) h4[t + i * 256] = z;
    }
    __syncthreads();
    if (t < KTOP) {
        hrow[si[t]] = sv[t];
        g_topi[(size_t)row * KTOP + t] = si[t];
        g_topv[(size_t)row * KTOP + t] = sv[t];
    }
}

// ---------------- kernel 6: sparse decoder ------------------------------------
__global__ __launch_bounds__(256) void decode_kernel(
    const float* __restrict__ bdec, float* __restrict__ xhat_out) {
    __shared__ int sid[KTOP];
    __shared__ float sval[KTOP];
    const int row = blockIdx.x;
    const int t = threadIdx.x;
    if (t < KTOP) {
        sid[t] = g_topi[(size_t)row * KTOP + t];
        sval[t] = g_topv[(size_t)row * KTOP + t];
    }
    __syncthreads();

    const int base = t * 8;
    float4 a0 = ((const float4*)(bdec + base))[0];
    float4 a1 = ((const float4*)(bdec + base))[1];
#pragma unroll 4
    for (int j = 0; j < KTOP; j++) {
        float v = sval[j];
        const float4* wr = (const float4*)(g_wdt + (size_t)sid[j] * DIN + base);
        float4 w0 = wr[0], w1 = wr[1];
        a0.x += v * w0.x; a0.y += v * w0.y; a0.z += v * w0.z; a0.w += v * w0.w;
        a1.x += v * w1.x; a1.y += v * w1.y; a1.z += v * w1.z; a1.w += v * w1.w;
    }
    float4* o = (float4*)(xhat_out + (size_t)row * DIN + base);
    o[0] = a0; o[1] = a1;
}

// ---------------- launch -------------------------------------------------------
extern "C" void kernel_launch(void* const* d_in, const int* in_sizes, int n_in,
                              void* d_out, int out_size) {
    const float* x    = (const float*)d_in[0];
    const float* Wenc = (const float*)d_in[1];
    const float* benc = (const float*)d_in[2];
    const float* Wdec = (const float*)d_in[3];
    const float* bdec = (const float*)d_in[4];

    float* h    = (float*)d_out;
    float* xhat = h + (size_t)BATCH * HID;

    {
        size_t n4 = (size_t)BATCH * DIN / 4;
        conv_h_kernel<<<(unsigned)((n4 + 1023) / 1024), 256>>>(x, 0, n4);
    }
    {
        size_t n4 = (size_t)HID * DIN / 4;
        conv_h_kernel<<<8192, 256>>>(Wenc, 1, n4);
    }
    transpose_wdec_kernel<<<dim3(HID / 32, DIN / 32), dim3(32, 8)>>>(Wdec);
    gemm_enc_kernel<<<dim3(BATCH / BM, HID / BN), 256>>>(benc);
    select_kernel<<<BATCH, 256>>>(x, Wenc, benc, h);
    decode_kernel<<<BATCH, 256>>>(bdec, xhat);
}

// round 13
// speedup vs baseline: 1.1403x; 1.0679x over previous
#include <cuda_runtime.h>
#include <cuda_bf16.h>
#include <cuda_fp16.h>
#include <cstdint>

// Problem constants
#define BATCH   4096
#define DIN     2048
#define HID     16384
#define KTOP    64
#define TSEL    72
#define CAP     256

// ---------------- scratch -----------------------------------------------------
__device__ __nv_bfloat16  g_xb[(size_t)BATCH * DIN];          // 16 MB
__device__ __nv_bfloat16  g_wb[(size_t)HID * DIN];            // 64 MB
__device__ unsigned short g_keys[(size_t)BATCH * HID];        // 128 MB
__device__ __half         g_wdt[(size_t)HID * DIN];           // 64 MB (fp16 W_decT)
__device__ int            g_topi[(size_t)BATCH * KTOP];
__device__ float          g_topv[(size_t)BATCH * KTOP];

// ---------------- helpers -----------------------------------------------------
__device__ __forceinline__ unsigned su32(const void* p) {
    return (unsigned)__cvta_generic_to_shared(p);
}
__device__ __forceinline__ unsigned short f2key16(float f) {
    unsigned u = __float_as_uint(f);
    u = (u & 0x80000000u) ? ~u : (u | 0x80000000u);
    return (unsigned short)(u >> 16);
}

#define CP16(dst, src) asm volatile( \
    "cp.async.cg.shared.global [%0], [%1], 16;\n" :: "r"(dst), "l"(src))
#define CP_COMMIT() asm volatile("cp.async.commit_group;\n" ::)
#define CP_WAIT(N)  asm volatile("cp.async.wait_group %0;\n" :: "n"(N))

// ---------------- kernels 1/2: fp32 -> bf16 -----------------------------------
__global__ void conv_bf16_kernel(const float* __restrict__ in, int which, size_t n4) {
    __nv_bfloat16* out = which ? g_wb : g_xb;
    __nv_bfloat162* o2 = (__nv_bfloat162*)out;
    for (size_t i = (size_t)blockIdx.x * blockDim.x + threadIdx.x;
         i < n4; i += (size_t)gridDim.x * blockDim.x) {
        float4 v = ((const float4*)in)[i];
        o2[2 * i]     = __nv_bfloat162(__float2bfloat16_rn(v.x), __float2bfloat16_rn(v.y));
        o2[2 * i + 1] = __nv_bfloat162(__float2bfloat16_rn(v.z), __float2bfloat16_rn(v.w));
    }
}

// ---------------- kernel 3: transpose W_dec -> fp16 W_decT ---------------------
__global__ void transpose_wdec_kernel(const float* __restrict__ W) {
    __shared__ float tile[32][33];
    int j0 = blockIdx.x * 32, d0 = blockIdx.y * 32;
    int tx = threadIdx.x, ty = threadIdx.y;
#pragma unroll
    for (int r = 0; r < 32; r += 8)
        tile[ty + r][tx] = W[(size_t)(d0 + ty + r) * HID + j0 + tx];
    __syncthreads();
#pragma unroll
    for (int r = 0; r < 32; r += 8)
        g_wdt[(size_t)(j0 + ty + r) * DIN + d0 + tx] = __float2half_rn(tile[tx][ty + r]);
}

// ---------------- kernel 4: bf16 mma.sync GEMM (f32 acc) -> u16 keys -----------
#define BM 128
#define BN 128
#define BK 32
#define LDS 40   // padded bf16 row (80B stride)

__global__ __launch_bounds__(256) void gemm_enc_kernel(const float* __restrict__ benc) {
    __shared__ __align__(16) __nv_bfloat16 As[2][BM * LDS];
    __shared__ __align__(16) __nv_bfloat16 Bs[2][BN * LDS];

    const int t = threadIdx.x;
    const int lane = t & 31, wid = t >> 5;
    const int wm = wid & 1, wn = wid >> 1;         // 2 x 4 warp grid, warp tile 64x32
    const int bm = blockIdx.x, bn = blockIdx.y;

    float acc[4][4][4];
#pragma unroll
    for (int i = 0; i < 4; i++)
#pragma unroll
        for (int j = 0; j < 4; j++)
#pragma unroll
            for (int r = 0; r < 4; r++) acc[i][j][r] = 0.f;

    auto load_stage = [&](int s, int kt) {
#pragma unroll
        for (int i = 0; i < 2; i++) {
            int cid = i * 256 + t;
            int row = cid >> 2, ch = cid & 3;
            const __nv_bfloat16* srcA = g_xb + (size_t)(bm * BM + row) * DIN + kt * BK + ch * 8;
            CP16(su32(&As[s][row * LDS + ch * 8]), srcA);
        }
#pragma unroll
        for (int i = 0; i < 2; i++) {
            int cid = i * 256 + t;
            int row = cid >> 2, ch = cid & 3;
            const __nv_bfloat16* srcB = g_wb + (size_t)(bn * BN + row) * DIN + kt * BK + ch * 8;
            CP16(su32(&Bs[s][row * LDS + ch * 8]), srcB);
        }
        CP_COMMIT();
    };

    auto compute = [&](int s) {
#pragma unroll
        for (int ks = 0; ks < 2; ks++) {
            unsigned a[4][4], b[4][2];
#pragma unroll
            for (int im = 0; im < 4; im++) {
                unsigned addr = su32(&As[s][(wm * 64 + im * 16 + (lane & 15)) * LDS +
                                            ks * 16 + (lane >> 4) * 8]);
                asm volatile("ldmatrix.sync.aligned.m8n8.x4.shared.b16 {%0,%1,%2,%3}, [%4];"
                             : "=r"(a[im][0]), "=r"(a[im][1]), "=r"(a[im][2]), "=r"(a[im][3])
                             : "r"(addr));
            }
#pragma unroll
            for (int in = 0; in < 4; in++) {
                unsigned addr = su32(&Bs[s][(wn * 32 + in * 8 + (lane & 7)) * LDS +
                                            ks * 16 + ((lane >> 3) & 1) * 8]);
                asm volatile("ldmatrix.sync.aligned.m8n8.x2.shared.b16 {%0,%1}, [%2];"
                             : "=r"(b[in][0]), "=r"(b[in][1]) : "r"(addr));
            }
#pragma unroll
            for (int im = 0; im < 4; im++)
#pragma unroll
                for (int in = 0; in < 4; in++) {
                    asm volatile(
                        "mma.sync.aligned.m16n8k16.row.col.f32.bf16.bf16.f32 "
                        "{%0,%1,%2,%3}, {%4,%5,%6,%7}, {%8,%9}, {%0,%1,%2,%3};"
                        : "+f"(acc[im][in][0]), "+f"(acc[im][in][1]),
                          "+f"(acc[im][in][2]), "+f"(acc[im][in][3])
                        : "r"(a[im][0]), "r"(a[im][1]), "r"(a[im][2]), "r"(a[im][3]),
                          "r"(b[in][0]), "r"(b[in][1]));
                }
        }
    };

    const int KT = DIN / BK;  // 64
    load_stage(0, 0);
    for (int kt = 0; kt < KT; kt++) {
        int cur = kt & 1;
        if (kt + 1 < KT) {
            load_stage(cur ^ 1, kt + 1);
            CP_WAIT(1);
        } else {
            CP_WAIT(0);
        }
        __syncthreads();
        compute(cur);
        __syncthreads();
    }

    const int r0base = bm * BM + wm * 64;
    const int c0base = bn * BN + wn * 32;
#pragma unroll
    for (int im = 0; im < 4; im++) {
#pragma unroll
        for (int in = 0; in < 4; in++) {
            int r0 = r0base + im * 16 + (lane >> 2);
            int c0 = c0base + in * 8 + (lane & 3) * 2;
            float b0 = benc[c0], b1 = benc[c0 + 1];
            unsigned p0 = (unsigned)f2key16(acc[im][in][0] + b0) |
                          ((unsigned)f2key16(acc[im][in][1] + b1) << 16);
            unsigned p1 = (unsigned)f2key16(acc[im][in][2] + b0) |
                          ((unsigned)f2key16(acc[im][in][3] + b1) << 16);
            *(unsigned*)(g_keys + (size_t)r0 * HID + c0) = p0;
            *(unsigned*)(g_keys + (size_t)(r0 + 8) * HID + c0) = p1;
        }
    }
}

// ---------------- kernel 5: per-row select + exact recompute + h write ---------
__global__ __launch_bounds__(256) void select_kernel(
    const float* __restrict__ x, const float* __restrict__ Wenc,
    const float* __restrict__ benc, float* __restrict__ h_out) {

    __shared__ __align__(16) unsigned short sk[HID];
    __shared__ __align__(16) float xs[DIN];
    __shared__ int hist[256];
    __shared__ int cidx[CAP];
    __shared__ float cval[CAP];
    __shared__ float sv[256];
    __shared__ int si[256];
    __shared__ int s_cnt, s_selhi, s_rem;
    __shared__ unsigned s_thr;

    const int row = blockIdx.x;
    const int t = threadIdx.x;
    const int lane = t & 31, wid = t >> 5;

    {
        const uint4* gk = (const uint4*)(g_keys + (size_t)row * HID);
        uint4* skv = (uint4*)sk;
#pragma unroll
        for (int i = 0; i < 8; i++) skv[t + i * 256] = gk[t + i * 256];
        const float4* gx = (const float4*)(x + (size_t)row * DIN);
        float4* xsv = (float4*)xs;
        xsv[t] = gx[t];
        xsv[t + 256] = gx[t + 256];
    }
    hist[t] = 0;
    if (t == 0) s_cnt = 0;
    __syncthreads();

    for (int i = t; i < HID; i += 256) atomicAdd(&hist[sk[i] >> 8], 1);
    __syncthreads();
    if (t == 0) {
        int cum = 0;
        s_selhi = 0; s_rem = TSEL;
        for (int b = 255; b >= 0; b--) {
            int hb = hist[b];
            if (cum + hb >= TSEL) { s_selhi = b; s_rem = TSEL - cum; break; }
            cum += hb;
        }
    }
    __syncthreads();
    int selhi = s_selhi, rem = s_rem;
    hist[t] = 0;
    __syncthreads();

    for (int i = t; i < HID; i += 256) {
        unsigned k = sk[i];
        if ((int)(k >> 8) == selhi) atomicAdd(&hist[k & 255], 1);
    }
    __syncthreads();
    if (t == 0) {
        int cum = 0, sello = 0;
        for (int b = 255; b >= 0; b--) {
            int hb = hist[b];
            if (cum + hb >= rem) { sello = b; break; }
            cum += hb;
        }
        s_thr = ((unsigned)selhi << 8) | (unsigned)sello;
    }
    __syncthreads();
    unsigned thr = s_thr;

    for (int i = t; i < HID; i += 256) {
        if ((unsigned)sk[i] >= thr) {
            int p = atomicAdd(&s_cnt, 1);
            if (p < CAP) cidx[p] = i;
        }
    }
    __syncthreads();
    int C = s_cnt < CAP ? s_cnt : CAP;

    const float4* xs4 = (const float4*)xs;
    for (int c = wid; c < C; c += 8) {
        int idx = cidx[c];
        const float4* w4 = (const float4*)(Wenc + (size_t)idx * DIN);
        float s = 0.f;
#pragma unroll 4
        for (int i = lane; i < DIN / 4; i += 32) {
            float4 w = w4[i], xv = xs4[i];
            s += w.x * xv.x + w.y * xv.y + w.z * xv.z + w.w * xv.w;
        }
#pragma unroll
        for (int off = 16; off; off >>= 1) s += __shfl_xor_sync(0xffffffffu, s, off);
        if (lane == 0) cval[c] = s + benc[idx];
    }
    __syncthreads();

    sv[t] = (t < C) ? cval[t] : -__int_as_float(0x7f800000);
    si[t] = (t < C) ? cidx[t] : 0x7fffffff;
    __syncthreads();
    for (int k = 2; k <= 256; k <<= 1) {
        for (int j = k >> 1; j > 0; j >>= 1) {
            int ixj = t ^ j;
            if (ixj > t) {
                float v1 = sv[t], v2 = sv[ixj];
                int i1 = si[t], i2 = si[ixj];
                bool g = (v1 > v2) || (v1 == v2 && i1 < i2);
                bool dirDesc = ((t & k) == 0);
                if (dirDesc ? (!g) : g) {
                    sv[t] = v2; sv[ixj] = v1;
                    si[t] = i2; si[ixj] = i1;
                }
            }
            __syncthreads();
        }
    }

    float* hrow = h_out + (size_t)row * HID;
    {
        float4 z = make_float4(0.f, 0.f, 0.f, 0.f);
        float4* h4 = (float4*)hrow;
#pragma unroll
        for (int i = 0; i < 16; i++) h4[t + i * 256] = z;
    }
    __syncthreads();
    if (t < KTOP) {
        hrow[si[t]] = sv[t];
        g_topi[(size_t)row * KTOP + t] = si[t];
        g_topv[(size_t)row * KTOP + t] = sv[t];
    }
}

// ---------------- kernel 6: sparse decoder (fp16 weights, fp32 accum) ----------
__global__ __launch_bounds__(256) void decode_kernel(
    const float* __restrict__ bdec, float* __restrict__ xhat_out) {
    __shared__ int sid[KTOP];
    __shared__ float sval[KTOP];
    const int row = blockIdx.x;
    const int t = threadIdx.x;
    if (t < KTOP) {
        sid[t] = g_topi[(size_t)row * KTOP + t];
        sval[t] = g_topv[(size_t)row * KTOP + t];
    }
    __syncthreads();

    const int base = t * 8;
    float4 a0 = ((const float4*)(bdec + base))[0];
    float4 a1 = ((const float4*)(bdec + base))[1];
#pragma unroll 4
    for (int j = 0; j < KTOP; j++) {
        float v = sval[j];
        uint4 wp = *(const uint4*)(g_wdt + (size_t)sid[j] * DIN + base);  // 8 fp16
        float2 w0 = __half22float2(*(__half2*)&wp.x);
        float2 w1 = __half22float2(*(__half2*)&wp.y);
        float2 w2 = __half22float2(*(__half2*)&wp.z);
        float2 w3 = __half22float2(*(__half2*)&wp.w);
        a0.x += v * w0.x; a0.y += v * w0.y; a0.z += v * w1.x; a0.w += v * w1.y;
        a1.x += v * w2.x; a1.y += v * w2.y; a1.z += v * w3.x; a1.w += v * w3.y;
    }
    float4* o = (float4*)(xhat_out + (size_t)row * DIN + base);
    o[0] = a0; o[1] = a1;
}

// ---------------- launch -------------------------------------------------------
extern "C" void kernel_launch(void* const* d_in, const int* in_sizes, int n_in,
                              void* d_out, int out_size) {
    const float* x    = (const float*)d_in[0];
    const float* Wenc = (const float*)d_in[1];
    const float* benc = (const float*)d_in[2];
    const float* Wdec = (const float*)d_in[3];
    const float* bdec = (const float*)d_in[4];

    float* h    = (float*)d_out;
    float* xhat = h + (size_t)BATCH * HID;

    {
        size_t n4 = (size_t)BATCH * DIN / 4;
        conv_bf16_kernel<<<(unsigned)((n4 + 1023) / 1024), 256>>>(x, 0, n4);
    }
    {
        size_t n4 = (size_t)HID * DIN / 4;
        conv_bf16_kernel<<<8192, 256>>>(Wenc, 1, n4);
    }
    transpose_wdec_kernel<<<dim3(HID / 32, DIN / 32), dim3(32, 8)>>>(Wdec);
    gemm_enc_kernel<<<dim3(BATCH / BM, HID / BN), 256>>>(benc);
    select_kernel<<<BATCH, 256>>>(x, Wenc, benc, h);
    decode_kernel<<<BATCH, 256>>>(bdec, xhat);
}